// round 1
// baseline (speedup 1.0000x reference)
#include <cuda_runtime.h>

#define N_NODES 50000
#define N_EDGES 600000

// Scratch: __device__ globals (no allocation allowed in kernel_launch).
__device__ float g_acc1[N_NODES * 128];  // segment_sum(x[src]) per dst
__device__ float g_h2  [N_NODES * 64];   // after Dense1
__device__ float g_acc2[N_NODES * 64];   // segment_sum(h2[src]) per dst

// ---------------------------------------------------------------------------
// Kernel 0: zero both accumulators (float4 stores, grid-stride)
// ---------------------------------------------------------------------------
__global__ void zero_kernel() {
    float4* a = reinterpret_cast<float4*>(g_acc1);
    float4* b = reinterpret_cast<float4*>(g_acc2);
    const int n1 = N_NODES * 128 / 4;
    const int n2 = N_NODES * 64 / 4;
    const int stride = gridDim.x * blockDim.x;
    const float4 z = make_float4(0.f, 0.f, 0.f, 0.f);
    for (int i = blockIdx.x * blockDim.x + threadIdx.x; i < n1; i += stride) a[i] = z;
    for (int i = blockIdx.x * blockDim.x + threadIdx.x; i < n2; i += stride) b[i] = z;
}

// ---------------------------------------------------------------------------
// Kernel 1: SpMM1 — one warp per edge, 128 feats, float4 gather + 4 atomics
// ---------------------------------------------------------------------------
__global__ void spmm1_kernel(const float* __restrict__ x,
                             const int* __restrict__ src,
                             const int* __restrict__ dst) {
    int e = (blockIdx.x * blockDim.x + threadIdx.x) >> 5;
    if (e >= N_EDGES) return;
    int lane = threadIdx.x & 31;
    int s = src[e];
    int d = dst[e];
    float4 v = *reinterpret_cast<const float4*>(x + (size_t)s * 128 + lane * 4);
    float* o = g_acc1 + (size_t)d * 128 + lane * 4;
    atomicAdd(o + 0, v.x);
    atomicAdd(o + 1, v.y);
    atomicAdd(o + 2, v.z);
    atomicAdd(o + 3, v.w);
}

// ---------------------------------------------------------------------------
// Kernel 2: h2 = (acc1 * w1) @ Wd1 + b1
//   Fold w1 into the smem copy of Wd1: (h*w1)@W == h@(diag(w1)W).
//   256 threads/block, 4 nodes/block, thread = (local_node, out_col).
// ---------------------------------------------------------------------------
__global__ void dense1_kernel(const float* __restrict__ w1,
                              const float* __restrict__ Wd1,
                              const float* __restrict__ b1) {
    __shared__ float Ws[128 * 64];
    __shared__ float bs[64];
    int tid = threadIdx.x;
    for (int i = tid; i < 128 * 64; i += 256) Ws[i] = Wd1[i] * w1[i >> 6];
    if (tid < 64) bs[tid] = b1[tid];
    __syncthreads();

    int col  = tid & 63;
    int node = blockIdx.x * 4 + (tid >> 6);
    if (node >= N_NODES) return;

    const float4* hrow = reinterpret_cast<const float4*>(g_acc1 + (size_t)node * 128);
    float sum = bs[col];
#pragma unroll
    for (int k = 0; k < 32; k++) {
        float4 h = hrow[k];
        sum = fmaf(h.x, Ws[(4 * k + 0) * 64 + col], sum);
        sum = fmaf(h.y, Ws[(4 * k + 1) * 64 + col], sum);
        sum = fmaf(h.z, Ws[(4 * k + 2) * 64 + col], sum);
        sum = fmaf(h.w, Ws[(4 * k + 3) * 64 + col], sum);
    }
    g_h2[(size_t)node * 64 + col] = sum;
}

// ---------------------------------------------------------------------------
// Kernel 3: SpMM2 — one warp per edge, 64 feats, float2 gather + 2 atomics
// ---------------------------------------------------------------------------
__global__ void spmm2_kernel(const int* __restrict__ src,
                             const int* __restrict__ dst) {
    int e = (blockIdx.x * blockDim.x + threadIdx.x) >> 5;
    if (e >= N_EDGES) return;
    int lane = threadIdx.x & 31;
    int s = src[e];
    int d = dst[e];
    float2 v = *reinterpret_cast<const float2*>(g_h2 + (size_t)s * 64 + lane * 2);
    float* o = g_acc2 + (size_t)d * 64 + lane * 2;
    atomicAdd(o + 0, v.x);
    atomicAdd(o + 1, v.y);
}

// ---------------------------------------------------------------------------
// Kernel 4: out = softmax(((acc2 * w2) @ Wd2 + b2) @ Wout + bout)
//   One warp per node. Lane j computes h3[j] (j<32). Then 4 logits via
//   butterfly reductions, softmax, lane 0 writes float4.
// ---------------------------------------------------------------------------
__global__ void final_kernel(const float* __restrict__ w2,
                             const float* __restrict__ Wd2,
                             const float* __restrict__ b2,
                             const float* __restrict__ Wout,
                             const float* __restrict__ bout,
                             float* __restrict__ out) {
    __shared__ float Ws[64 * 32];   // diag(w2) @ Wd2
    __shared__ float Wo[32 * 4];
    __shared__ float b2s[32];
    __shared__ float bos[4];
    int tid = threadIdx.x;
    for (int i = tid; i < 64 * 32; i += 256) Ws[i] = Wd2[i] * w2[i >> 5];
    if (tid < 128) Wo[tid]  = Wout[tid];
    if (tid < 32)  b2s[tid] = b2[tid];
    if (tid < 4)   bos[tid] = bout[tid];
    __syncthreads();

    int lane = tid & 31;
    int node = blockIdx.x * 8 + (tid >> 5);
    if (node >= N_NODES) return;

    const float4* a4 = reinterpret_cast<const float4*>(g_acc2 + (size_t)node * 64);
    float h = b2s[lane];
#pragma unroll
    for (int k4 = 0; k4 < 16; k4++) {
        float4 a = a4[k4];
        h = fmaf(a.x, Ws[(4 * k4 + 0) * 32 + lane], h);
        h = fmaf(a.y, Ws[(4 * k4 + 1) * 32 + lane], h);
        h = fmaf(a.z, Ws[(4 * k4 + 2) * 32 + lane], h);
        h = fmaf(a.w, Ws[(4 * k4 + 3) * 32 + lane], h);
    }

    float logit[4];
#pragma unroll
    for (int c = 0; c < 4; c++) {
        float p = h * Wo[lane * 4 + c];
#pragma unroll
        for (int off = 16; off > 0; off >>= 1)
            p += __shfl_xor_sync(0xffffffffu, p, off);
        logit[c] = p + bos[c];
    }

    float m = fmaxf(fmaxf(logit[0], logit[1]), fmaxf(logit[2], logit[3]));
    float e0 = __expf(logit[0] - m);
    float e1 = __expf(logit[1] - m);
    float e2 = __expf(logit[2] - m);
    float e3 = __expf(logit[3] - m);
    float inv = 1.0f / (e0 + e1 + e2 + e3);
    if (lane == 0) {
        float4 r = make_float4(e0 * inv, e1 * inv, e2 * inv, e3 * inv);
        *reinterpret_cast<float4*>(out + (size_t)node * 4) = r;
    }
}

// ---------------------------------------------------------------------------
// Launch
// Inputs (metadata order): x, src, dst, w1, Wd1, b1, w2, Wd2, b2, Wout, bout
// ---------------------------------------------------------------------------
extern "C" void kernel_launch(void* const* d_in, const int* in_sizes, int n_in,
                              void* d_out, int out_size) {
    const float* x    = (const float*)d_in[0];
    const int*   src  = (const int*)  d_in[1];
    const int*   dst  = (const int*)  d_in[2];
    const float* w1   = (const float*)d_in[3];
    const float* Wd1  = (const float*)d_in[4];
    const float* b1   = (const float*)d_in[5];
    const float* w2   = (const float*)d_in[6];
    const float* Wd2  = (const float*)d_in[7];
    const float* b2   = (const float*)d_in[8];
    const float* Wout = (const float*)d_in[9];
    const float* bout = (const float*)d_in[10];
    float* out = (float*)d_out;

    zero_kernel<<<148 * 8, 256>>>();

    // 600000 warps, 8 warps/block -> 75000 blocks (exact)
    spmm1_kernel<<<75000, 256>>>(x, src, dst);

    // 50000 nodes, 4 nodes/block -> 12500 blocks (exact)
    dense1_kernel<<<12500, 256>>>(w1, Wd1, b1);

    spmm2_kernel<<<75000, 256>>>(src, dst);

    // 50000 nodes, 8 warps/block -> 6250 blocks (exact)
    final_kernel<<<6250, 256>>>(w2, Wd2, b2, Wout, bout, out);
}

// round 2
// speedup vs baseline: 4.0079x; 4.0079x over previous
#include <cuda_runtime.h>

#define NN 50000
#define NE 600000
#define NCH 196          // ceil(NN/256)

// ---------------- scratch (__device__ globals; no allocs allowed) ----------
__device__ float g_Y1[NN * 64];      // x @ (diag(w1) Wd1)
__device__ float g_h1[NN * 64];      // A @ Y1 + b1
__device__ float g_Y2[NN * 32];      // h1 @ (diag(w2) Wd2)
__device__ int   g_deg[NN];
__device__ int   g_rs[NN];           // CSR row start
__device__ int   g_cur[NN];          // fill cursors
__device__ int   g_chunkSum[256];
__device__ int   g_chunkOff[256];
__device__ int   g_esrc[NE];         // src ids sorted by dst

// ---------------------------------------------------------------------------
__global__ void k_zero_deg() {
    int i = blockIdx.x * 256 + threadIdx.x;
    if (i < NN) g_deg[i] = 0;
}

__global__ void k_hist(const int* __restrict__ dst) {
    int i = blockIdx.x * 256 + threadIdx.x;
    if (i < NE) atomicAdd(&g_deg[dst[i]], 1);
}

// Block-level inclusive scan helpers (Hillis-Steele over 256)
__global__ void k_scan_a() {
    __shared__ int sh[256];
    int t = threadIdx.x, b = blockIdx.x;
    int i = b * 256 + t;
    int d = (i < NN) ? g_deg[i] : 0;
    sh[t] = d;
    __syncthreads();
    for (int off = 1; off < 256; off <<= 1) {
        int add = (t >= off) ? sh[t - off] : 0;
        __syncthreads();
        sh[t] += add;
        __syncthreads();
    }
    int incl = sh[t];
    if (i < NN) g_rs[i] = incl - d;          // local exclusive
    if (t == 255) g_chunkSum[b] = incl;      // block total
}

__global__ void k_scan_b() {
    __shared__ int sh[256];
    int t = threadIdx.x;
    int v = (t < NCH) ? g_chunkSum[t] : 0;
    sh[t] = v;
    __syncthreads();
    for (int off = 1; off < 256; off <<= 1) {
        int add = (t >= off) ? sh[t - off] : 0;
        __syncthreads();
        sh[t] += add;
        __syncthreads();
    }
    if (t < NCH) g_chunkOff[t] = sh[t] - v;  // exclusive
}

__global__ void k_scan_c() {
    int b = blockIdx.x, t = threadIdx.x;
    int i = b * 256 + t;
    if (i < NN) {
        int v = g_rs[i] + g_chunkOff[b];
        g_rs[i]  = v;
        g_cur[i] = v;
    }
}

__global__ void k_fill(const int* __restrict__ src, const int* __restrict__ dst) {
    int i = blockIdx.x * 256 + threadIdx.x;
    if (i < NE) {
        int p = atomicAdd(&g_cur[dst[i]], 1);
        g_esrc[p] = src[i];
    }
}

// ---------------------------------------------------------------------------
// Y1 = x @ (diag(w1) Wd1)   (128 -> 64), register-tiled 4x4
// block = 256 threads, 64 nodes/block
// ---------------------------------------------------------------------------
__global__ void k_dense1(const float* __restrict__ x,
                         const float* __restrict__ w1,
                         const float* __restrict__ Wd1) {
    __shared__ float Ws[128 * 64];       // 32 KB, folded weight
    __shared__ float xs[64 * 132];       // 64 rows, stride 132 (pad)
    int tid = threadIdx.x;
    for (int i = tid; i < 128 * 64; i += 256) Ws[i] = Wd1[i] * w1[i >> 6];

    int node0 = blockIdx.x * 64;
    for (int i = tid; i < 64 * 32; i += 256) {     // 32 float4 per row
        int r = i >> 5, c = (i & 31) * 4;
        float4 v = make_float4(0.f, 0.f, 0.f, 0.f);
        if (node0 + r < NN)
            v = *reinterpret_cast<const float4*>(x + (size_t)(node0 + r) * 128 + c);
        *reinterpret_cast<float4*>(&xs[r * 132 + c]) = v;
    }
    __syncthreads();

    int tx = tid & 15, ty = tid >> 4;    // tx: 16 col groups, ty: 16 node groups
    int col = tx * 4;
    float acc[4][4] = {};
#pragma unroll 8
    for (int k = 0; k < 128; k++) {
        float4 wv = *reinterpret_cast<const float4*>(&Ws[k * 64 + col]);
#pragma unroll
        for (int i = 0; i < 4; i++) {
            float a = xs[(ty * 4 + i) * 132 + k];
            acc[i][0] = fmaf(a, wv.x, acc[i][0]);
            acc[i][1] = fmaf(a, wv.y, acc[i][1]);
            acc[i][2] = fmaf(a, wv.z, acc[i][2]);
            acc[i][3] = fmaf(a, wv.w, acc[i][3]);
        }
    }
#pragma unroll
    for (int i = 0; i < 4; i++) {
        int node = node0 + ty * 4 + i;
        if (node < NN)
            *reinterpret_cast<float4*>(g_Y1 + (size_t)node * 64 + col) =
                make_float4(acc[i][0], acc[i][1], acc[i][2], acc[i][3]);
    }
}

// ---------------------------------------------------------------------------
// h1 = gather-sum(Y1) + b1     (warp per node, 64 feats, float2/lane)
// ---------------------------------------------------------------------------
__global__ void k_gather1(const float* __restrict__ b1) {
    __shared__ float b1s[64];
    if (threadIdx.x < 64) b1s[threadIdx.x] = b1[threadIdx.x];
    __syncthreads();

    int node = (blockIdx.x * 256 + threadIdx.x) >> 5;
    if (node >= NN) return;
    int lane = threadIdx.x & 31;

    int p = g_rs[node], n = g_deg[node];
    float ax = 0.f, ay = 0.f, bx = 0.f, by = 0.f;
    int j = 0;
    for (; j + 2 <= n; j += 2) {
        int s0 = g_esrc[p + j];
        int s1 = g_esrc[p + j + 1];
        float2 v0 = *reinterpret_cast<const float2*>(g_Y1 + (size_t)s0 * 64 + lane * 2);
        float2 v1 = *reinterpret_cast<const float2*>(g_Y1 + (size_t)s1 * 64 + lane * 2);
        ax += v0.x; ay += v0.y;
        bx += v1.x; by += v1.y;
    }
    if (j < n) {
        int s = g_esrc[p + j];
        float2 v = *reinterpret_cast<const float2*>(g_Y1 + (size_t)s * 64 + lane * 2);
        ax += v.x; ay += v.y;
    }
    float2 r;
    r.x = ax + bx + b1s[lane * 2];
    r.y = ay + by + b1s[lane * 2 + 1];
    *reinterpret_cast<float2*>(g_h1 + (size_t)node * 64 + lane * 2) = r;
}

// ---------------------------------------------------------------------------
// Y2 = h1 @ (diag(w2) Wd2)   (64 -> 32), register-tiled 2x4
// block = 256 threads, 64 nodes/block
// ---------------------------------------------------------------------------
__global__ void k_dense2(const float* __restrict__ w2,
                         const float* __restrict__ Wd2) {
    __shared__ float Ws[64 * 32];        // 8 KB
    __shared__ float xs[64 * 68];        // pad 68
    int tid = threadIdx.x;
    for (int i = tid; i < 64 * 32; i += 256) Ws[i] = Wd2[i] * w2[i >> 5];

    int node0 = blockIdx.x * 64;
    for (int i = tid; i < 64 * 16; i += 256) {     // 16 float4 per row
        int r = i >> 4, c = (i & 15) * 4;
        float4 v = make_float4(0.f, 0.f, 0.f, 0.f);
        if (node0 + r < NN)
            v = *reinterpret_cast<const float4*>(g_h1 + (size_t)(node0 + r) * 64 + c);
        *reinterpret_cast<float4*>(&xs[r * 68 + c]) = v;
    }
    __syncthreads();

    int tx = tid & 7, ty = tid >> 3;     // tx: 8 col groups, ty: 32
    int col = tx * 4;
    float acc[2][4] = {};
#pragma unroll 8
    for (int k = 0; k < 64; k++) {
        float4 wv = *reinterpret_cast<const float4*>(&Ws[k * 32 + col]);
#pragma unroll
        for (int i = 0; i < 2; i++) {
            float a = xs[(ty + 32 * i) * 68 + k];
            acc[i][0] = fmaf(a, wv.x, acc[i][0]);
            acc[i][1] = fmaf(a, wv.y, acc[i][1]);
            acc[i][2] = fmaf(a, wv.z, acc[i][2]);
            acc[i][3] = fmaf(a, wv.w, acc[i][3]);
        }
    }
#pragma unroll
    for (int i = 0; i < 2; i++) {
        int node = node0 + ty + 32 * i;
        if (node < NN)
            *reinterpret_cast<float4*>(g_Y2 + (size_t)node * 32 + col) =
                make_float4(acc[i][0], acc[i][1], acc[i][2], acc[i][3]);
    }
}

// ---------------------------------------------------------------------------
// out = softmax((gather-sum(Y2) + b2) @ Wout + bout)   (warp per node)
// ---------------------------------------------------------------------------
__global__ void k_gather2_final(const float* __restrict__ b2,
                                const float* __restrict__ Wout,
                                const float* __restrict__ bout,
                                float* __restrict__ out) {
    __shared__ float b2s[32], Wo[128], bos[4];
    int tid = threadIdx.x;
    if (tid < 32)  b2s[tid] = b2[tid];
    if (tid < 128) Wo[tid]  = Wout[tid];
    if (tid < 4)   bos[tid] = bout[tid];
    __syncthreads();

    int node = (blockIdx.x * 256 + tid) >> 5;
    if (node >= NN) return;
    int lane = tid & 31;

    int p = g_rs[node], n = g_deg[node];
    float a0 = 0.f, a1 = 0.f;
    int j = 0;
    for (; j + 2 <= n; j += 2) {
        int s0 = g_esrc[p + j];
        int s1 = g_esrc[p + j + 1];
        a0 += g_Y2[(size_t)s0 * 32 + lane];
        a1 += g_Y2[(size_t)s1 * 32 + lane];
    }
    if (j < n) a0 += g_Y2[(size_t)g_esrc[p + j] * 32 + lane];
    float h = a0 + a1 + b2s[lane];

    float logit[4];
#pragma unroll
    for (int c = 0; c < 4; c++) {
        float psum = h * Wo[lane * 4 + c];
#pragma unroll
        for (int off = 16; off > 0; off >>= 1)
            psum += __shfl_xor_sync(0xffffffffu, psum, off);
        logit[c] = psum + bos[c];
    }

    float m = fmaxf(fmaxf(logit[0], logit[1]), fmaxf(logit[2], logit[3]));
    float e0 = __expf(logit[0] - m);
    float e1 = __expf(logit[1] - m);
    float e2 = __expf(logit[2] - m);
    float e3 = __expf(logit[3] - m);
    float inv = 1.0f / (e0 + e1 + e2 + e3);
    if (lane == 0)
        *reinterpret_cast<float4*>(out + (size_t)node * 4) =
            make_float4(e0 * inv, e1 * inv, e2 * inv, e3 * inv);
}

// ---------------------------------------------------------------------------
// Launch.  Inputs: x, src, dst, w1, Wd1, b1, w2, Wd2, b2, Wout, bout
// ---------------------------------------------------------------------------
extern "C" void kernel_launch(void* const* d_in, const int* in_sizes, int n_in,
                              void* d_out, int out_size) {
    const float* x    = (const float*)d_in[0];
    const int*   src  = (const int*)  d_in[1];
    const int*   dst  = (const int*)  d_in[2];
    const float* w1   = (const float*)d_in[3];
    const float* Wd1  = (const float*)d_in[4];
    const float* b1   = (const float*)d_in[5];
    const float* w2   = (const float*)d_in[6];
    const float* Wd2  = (const float*)d_in[7];
    const float* b2   = (const float*)d_in[8];
    const float* Wout = (const float*)d_in[9];
    const float* bout = (const float*)d_in[10];
    float* out = (float*)d_out;

    const int EB = (NE + 255) / 256;   // 2344
    const int DB = (NN + 63) / 64;     // 782

    // CSR build
    k_zero_deg<<<NCH, 256>>>();
    k_hist<<<EB, 256>>>(dst);
    // dense projection (independent of CSR build order)
    k_dense1<<<DB, 256>>>(x, w1, Wd1);
    k_scan_a<<<NCH, 256>>>();
    k_scan_b<<<1, 256>>>();
    k_scan_c<<<NCH, 256>>>();
    k_fill<<<EB, 256>>>(src, dst);

    // layer 1 aggregate (64 feats)
    k_gather1<<<(NN * 32 + 255) / 256, 256>>>(b1);
    // layer 2 projection
    k_dense2<<<DB, 256>>>(w2, Wd2);
    // layer 2 aggregate (32 feats) + output head + softmax
    k_gather2_final<<<(NN * 32 + 255) / 256, 256>>>(b2, Wout, bout, out);
}

// round 3
// speedup vs baseline: 4.2783x; 1.0675x over previous
#include <cuda_runtime.h>

#define NN 50000
#define NE 600000
#define NCH 196          // ceil(NN/256)

typedef unsigned long long ull;

// ---------------- scratch (__device__ globals; no allocs allowed) ----------
__device__ float g_Y1[NN * 64];      // x @ (diag(w1) Wd1)
__device__ float g_h1[NN * 64];      // A @ Y1 + b1
__device__ float g_Y2[NN * 32];      // h1 @ (diag(w2) Wd2)
__device__ int   g_deg[NN];
__device__ int   g_rs[NN];           // CSR row start
__device__ int   g_cur[NN];          // fill cursors
__device__ int   g_partials[256];    // lookback scan state: (state<<30)|value
__device__ int   g_esrc[NE];         // src ids sorted by dst

// ---------------------------------------------------------------------------
__global__ void k_zero() {
    int i = blockIdx.x * 256 + threadIdx.x;
    if (i < NN)  g_deg[i] = 0;
    if (blockIdx.x == 0 && threadIdx.x < 256) g_partials[threadIdx.x] = 0;
}

// histogram over dst, int4-vectorized edge reads
__global__ void k_hist(const int* __restrict__ dst) {
    int i = blockIdx.x * 256 + threadIdx.x;
    if (i < NE / 4) {
        int4 d = reinterpret_cast<const int4*>(dst)[i];
        atomicAdd(&g_deg[d.x], 1);
        atomicAdd(&g_deg[d.y], 1);
        atomicAdd(&g_deg[d.z], 1);
        atomicAdd(&g_deg[d.w], 1);
    }
}

// ---------------------------------------------------------------------------
// Single-kernel exclusive scan of g_deg -> g_rs/g_cur (decoupled lookback)
// ---------------------------------------------------------------------------
__global__ void k_scan() {
    __shared__ int warpsum[8];
    __shared__ int sh_excl;
    int b = blockIdx.x, t = threadIdx.x;
    int lane = t & 31, wid = t >> 5;
    int i = b * 256 + t;
    int d = (i < NN) ? g_deg[i] : 0;

    // warp inclusive scan
    int v = d;
#pragma unroll
    for (int off = 1; off < 32; off <<= 1) {
        int nv = __shfl_up_sync(0xffffffffu, v, off);
        if (lane >= off) v += nv;
    }
    if (lane == 31) warpsum[wid] = v;
    __syncthreads();
    if (t < 32) {
        int s = (t < 8) ? warpsum[t] : 0;
#pragma unroll
        for (int off = 1; off < 8; off <<= 1) {
            int ns = __shfl_up_sync(0xffffffffu, s, off);
            if (t >= off) s += ns;
        }
        if (t < 8) warpsum[t] = s;    // inclusive warp sums
    }
    __syncthreads();
    int excl_in_block = v - d + (wid ? warpsum[wid - 1] : 0);
    int blocktotal = warpsum[7];

    // publish
    if (t == 0) {
        int st = (b == 0) ? ((2 << 30) | blocktotal) : ((1 << 30) | blocktotal);
        atomicExch(&g_partials[b], st);
        if (b == 0) sh_excl = 0;
    }

    // warp-parallel lookback (warp 0)
    if (b > 0 && t < 32) {
        int excl = 0;
        int j = b - 1;
        while (true) {
            int idx = j - lane;
            int raw = (idx >= 0) ? *(volatile int*)&g_partials[idx] : (2 << 30);
            int st = (unsigned)raw >> 30;
            int val = raw & ((1 << 30) - 1);
            unsigned prefmask = __ballot_sync(0xffffffffu, st == 2);
            unsigned zeromask = __ballot_sync(0xffffffffu, st == 0);
            int firstpref = prefmask ? (__ffs(prefmask) - 1) : 32;
            int firstzero = zeromask ? (__ffs(zeromask) - 1) : 32;
            if (firstzero < firstpref) continue;   // wait for predecessor
            if (firstpref < 32) {
                int contrib = (lane <= firstpref) ? val : 0;
#pragma unroll
                for (int off = 16; off; off >>= 1)
                    contrib += __shfl_xor_sync(0xffffffffu, contrib, off);
                excl += contrib;
                break;
            } else {
                int contrib = val;
#pragma unroll
                for (int off = 16; off; off >>= 1)
                    contrib += __shfl_xor_sync(0xffffffffu, contrib, off);
                excl += contrib;
                j -= 32;
            }
        }
        if (lane == 0) {
            atomicExch(&g_partials[b], (2 << 30) | (excl + blocktotal));
            sh_excl = excl;
        }
    }
    __syncthreads();
    int rsv = sh_excl + excl_in_block;
    if (i < NN) { g_rs[i] = rsv; g_cur[i] = rsv; }
}

__global__ void k_fill(const int* __restrict__ src, const int* __restrict__ dst) {
    int i = blockIdx.x * 256 + threadIdx.x;
    if (i < NE / 4) {
        int4 s = reinterpret_cast<const int4*>(src)[i];
        int4 d = reinterpret_cast<const int4*>(dst)[i];
        g_esrc[atomicAdd(&g_cur[d.x], 1)] = s.x;
        g_esrc[atomicAdd(&g_cur[d.y], 1)] = s.y;
        g_esrc[atomicAdd(&g_cur[d.z], 1)] = s.z;
        g_esrc[atomicAdd(&g_cur[d.w], 1)] = s.w;
    }
}

// ---------------------------------------------------------------------------
// Y1 = x @ (diag(w1) Wd1)   (128 -> 64), 64 nodes/block, 4 rows x 4 cols,
// cols paired into packed f32x2 FMAs.
// ---------------------------------------------------------------------------
__global__ void k_dense1(const float* __restrict__ x,
                         const float* __restrict__ w1,
                         const float* __restrict__ Wd1) {
    __shared__ float Ws[128 * 64];
    __shared__ float xs[64 * 132];
    int tid = threadIdx.x;
    for (int i = tid; i < 128 * 64; i += 256) Ws[i] = Wd1[i] * w1[i >> 6];

    int node0 = blockIdx.x * 64;
    for (int i = tid; i < 64 * 32; i += 256) {
        int r = i >> 5, c = (i & 31) * 4;
        float4 v = make_float4(0.f, 0.f, 0.f, 0.f);
        if (node0 + r < NN)
            v = *reinterpret_cast<const float4*>(x + (size_t)(node0 + r) * 128 + c);
        *reinterpret_cast<float4*>(&xs[r * 132 + c]) = v;
    }
    __syncthreads();

    int tx = tid & 15, ty = tid >> 4;
    int col = tx * 4;
    ull acc01[4] = {0, 0, 0, 0};
    ull acc23[4] = {0, 0, 0, 0};
#pragma unroll 4
    for (int k = 0; k < 128; k++) {
        ull w01 = *reinterpret_cast<const ull*>(Ws + k * 64 + col);
        ull w23 = *reinterpret_cast<const ull*>(Ws + k * 64 + col + 2);
#pragma unroll
        for (int i = 0; i < 4; i++) {
            float a = xs[(ty * 4 + i) * 132 + k];
            ull ap;
            asm("mov.b64 %0, {%1, %1};" : "=l"(ap) : "f"(a));
            asm("fma.rn.f32x2 %0, %1, %2, %0;" : "+l"(acc01[i]) : "l"(ap), "l"(w01));
            asm("fma.rn.f32x2 %0, %1, %2, %0;" : "+l"(acc23[i]) : "l"(ap), "l"(w23));
        }
    }
#pragma unroll
    for (int i = 0; i < 4; i++) {
        int node = node0 + ty * 4 + i;
        if (node < NN) {
            float2 lo = *reinterpret_cast<float2*>(&acc01[i]);
            float2 hi = *reinterpret_cast<float2*>(&acc23[i]);
            *reinterpret_cast<float4*>(g_Y1 + (size_t)node * 64 + col) =
                make_float4(lo.x, lo.y, hi.x, hi.y);
        }
    }
}

// ---------------------------------------------------------------------------
// h1 = gather-sum(Y1) + b1 : 2 nodes/warp, 16 lanes x float4, unroll 4
// ---------------------------------------------------------------------------
__device__ __forceinline__ void f4add(float4& a, const float4& b) {
    a.x += b.x; a.y += b.y; a.z += b.z; a.w += b.w;
}

__global__ void k_gather1(const float* __restrict__ b1) {
    int gw = (blockIdx.x * 256 + threadIdx.x) >> 5;
    int lane = threadIdx.x & 31;
    int half = lane >> 4, hl = lane & 15;
    int node = gw * 2 + half;
    if (node >= NN) return;

    int p = g_rs[node], n = g_deg[node];
    float4 a0 = make_float4(0.f, 0.f, 0.f, 0.f);
    float4 a1 = a0, a2 = a0, a3 = a0;
    int j = 0;
    for (; j + 4 <= n; j += 4) {
        int s0 = g_esrc[p + j];
        int s1 = g_esrc[p + j + 1];
        int s2 = g_esrc[p + j + 2];
        int s3 = g_esrc[p + j + 3];
        f4add(a0, *reinterpret_cast<const float4*>(g_Y1 + (size_t)s0 * 64 + hl * 4));
        f4add(a1, *reinterpret_cast<const float4*>(g_Y1 + (size_t)s1 * 64 + hl * 4));
        f4add(a2, *reinterpret_cast<const float4*>(g_Y1 + (size_t)s2 * 64 + hl * 4));
        f4add(a3, *reinterpret_cast<const float4*>(g_Y1 + (size_t)s3 * 64 + hl * 4));
    }
    for (; j < n; j++) {
        int s = g_esrc[p + j];
        f4add(a0, *reinterpret_cast<const float4*>(g_Y1 + (size_t)s * 64 + hl * 4));
    }
    float4 bb = *reinterpret_cast<const float4*>(b1 + hl * 4);
    float4 r;
    r.x = a0.x + a1.x + a2.x + a3.x + bb.x;
    r.y = a0.y + a1.y + a2.y + a3.y + bb.y;
    r.z = a0.z + a1.z + a2.z + a3.z + bb.z;
    r.w = a0.w + a1.w + a2.w + a3.w + bb.w;
    *reinterpret_cast<float4*>(g_h1 + (size_t)node * 64 + hl * 4) = r;
}

// ---------------------------------------------------------------------------
// Y2 = h1 @ (diag(w2) Wd2)   (64 -> 32), 64 nodes/block, 2 rows x 4 cols,
// packed f32x2.
// ---------------------------------------------------------------------------
__global__ void k_dense2(const float* __restrict__ w2,
                         const float* __restrict__ Wd2) {
    __shared__ float Ws[64 * 32];
    __shared__ float xs[64 * 68];
    int tid = threadIdx.x;
    for (int i = tid; i < 64 * 32; i += 256) Ws[i] = Wd2[i] * w2[i >> 5];

    int node0 = blockIdx.x * 64;
    for (int i = tid; i < 64 * 16; i += 256) {
        int r = i >> 4, c = (i & 15) * 4;
        float4 v = make_float4(0.f, 0.f, 0.f, 0.f);
        if (node0 + r < NN)
            v = *reinterpret_cast<const float4*>(g_h1 + (size_t)(node0 + r) * 64 + c);
        *reinterpret_cast<float4*>(&xs[r * 68 + c]) = v;
    }
    __syncthreads();

    int tx = tid & 7, ty = tid >> 3;
    int col = tx * 4;
    ull acc01[2] = {0, 0};
    ull acc23[2] = {0, 0};
#pragma unroll 4
    for (int k = 0; k < 64; k++) {
        ull w01 = *reinterpret_cast<const ull*>(Ws + k * 32 + col);
        ull w23 = *reinterpret_cast<const ull*>(Ws + k * 32 + col + 2);
#pragma unroll
        for (int i = 0; i < 2; i++) {
            float a = xs[(ty + 32 * i) * 68 + k];
            ull ap;
            asm("mov.b64 %0, {%1, %1};" : "=l"(ap) : "f"(a));
            asm("fma.rn.f32x2 %0, %1, %2, %0;" : "+l"(acc01[i]) : "l"(ap), "l"(w01));
            asm("fma.rn.f32x2 %0, %1, %2, %0;" : "+l"(acc23[i]) : "l"(ap), "l"(w23));
        }
    }
#pragma unroll
    for (int i = 0; i < 2; i++) {
        int node = node0 + ty + 32 * i;
        if (node < NN) {
            float2 lo = *reinterpret_cast<float2*>(&acc01[i]);
            float2 hi = *reinterpret_cast<float2*>(&acc23[i]);
            *reinterpret_cast<float4*>(g_Y2 + (size_t)node * 32 + col) =
                make_float4(lo.x, lo.y, hi.x, hi.y);
        }
    }
}

// ---------------------------------------------------------------------------
// out = softmax((gather-sum(Y2) + b2) @ Wout + bout)
// 4 nodes/warp, 8 lanes x float4, unroll 4
// ---------------------------------------------------------------------------
__global__ void k_gather2_final(const float* __restrict__ b2,
                                const float* __restrict__ Wout,
                                const float* __restrict__ bout,
                                float* __restrict__ out) {
    int gw = (blockIdx.x * 256 + threadIdx.x) >> 5;
    int lane = threadIdx.x & 31;
    int sub = lane >> 3, sl = lane & 7;
    int node = gw * 4 + sub;
    if (node >= NN) return;

    int p = g_rs[node], n = g_deg[node];
    float4 a0 = make_float4(0.f, 0.f, 0.f, 0.f);
    float4 a1 = a0, a2 = a0, a3 = a0;
    int j = 0;
    for (; j + 4 <= n; j += 4) {
        int s0 = g_esrc[p + j];
        int s1 = g_esrc[p + j + 1];
        int s2 = g_esrc[p + j + 2];
        int s3 = g_esrc[p + j + 3];
        f4add(a0, *reinterpret_cast<const float4*>(g_Y2 + (size_t)s0 * 32 + sl * 4));
        f4add(a1, *reinterpret_cast<const float4*>(g_Y2 + (size_t)s1 * 32 + sl * 4));
        f4add(a2, *reinterpret_cast<const float4*>(g_Y2 + (size_t)s2 * 32 + sl * 4));
        f4add(a3, *reinterpret_cast<const float4*>(g_Y2 + (size_t)s3 * 32 + sl * 4));
    }
    for (; j < n; j++) {
        int s = g_esrc[p + j];
        f4add(a0, *reinterpret_cast<const float4*>(g_Y2 + (size_t)s * 32 + sl * 4));
    }
    float4 bb = *reinterpret_cast<const float4*>(b2 + sl * 4);
    float4 h;
    h.x = a0.x + a1.x + a2.x + a3.x + bb.x;
    h.y = a0.y + a1.y + a2.y + a3.y + bb.y;
    h.z = a0.z + a1.z + a2.z + a3.z + bb.z;
    h.w = a0.w + a1.w + a2.w + a3.w + bb.w;

    float lg[4];
#pragma unroll
    for (int c = 0; c < 4; c++) {
        float ps = h.x * __ldg(Wout + (sl * 4 + 0) * 4 + c)
                 + h.y * __ldg(Wout + (sl * 4 + 1) * 4 + c)
                 + h.z * __ldg(Wout + (sl * 4 + 2) * 4 + c)
                 + h.w * __ldg(Wout + (sl * 4 + 3) * 4 + c);
#pragma unroll
        for (int off = 4; off; off >>= 1)
            ps += __shfl_xor_sync(0xffffffffu, ps, off);
        lg[c] = ps + __ldg(bout + c);
    }

    float m = fmaxf(fmaxf(lg[0], lg[1]), fmaxf(lg[2], lg[3]));
    float e0 = __expf(lg[0] - m);
    float e1 = __expf(lg[1] - m);
    float e2 = __expf(lg[2] - m);
    float e3 = __expf(lg[3] - m);
    float inv = 1.0f / (e0 + e1 + e2 + e3);
    if (sl == 0)
        *reinterpret_cast<float4*>(out + (size_t)node * 4) =
            make_float4(e0 * inv, e1 * inv, e2 * inv, e3 * inv);
}

// ---------------------------------------------------------------------------
// Launch.  Inputs: x, src, dst, w1, Wd1, b1, w2, Wd2, b2, Wout, bout
// ---------------------------------------------------------------------------
extern "C" void kernel_launch(void* const* d_in, const int* in_sizes, int n_in,
                              void* d_out, int out_size) {
    const float* x    = (const float*)d_in[0];
    const int*   src  = (const int*)  d_in[1];
    const int*   dst  = (const int*)  d_in[2];
    const float* w1   = (const float*)d_in[3];
    const float* Wd1  = (const float*)d_in[4];
    const float* b1   = (const float*)d_in[5];
    const float* w2   = (const float*)d_in[6];
    const float* Wd2  = (const float*)d_in[7];
    const float* b2   = (const float*)d_in[8];
    const float* Wout = (const float*)d_in[9];
    const float* bout = (const float*)d_in[10];
    float* out = (float*)d_out;

    const int EB4 = (NE / 4 + 255) / 256;   // 586
    const int DB  = (NN + 63) / 64;         // 782

    k_zero<<<NCH, 256>>>();
    k_hist<<<EB4, 256>>>(dst);
    k_dense1<<<DB, 256>>>(x, w1, Wd1);      // independent of CSR build
    k_scan<<<NCH, 256>>>();
    k_fill<<<EB4, 256>>>(src, dst);

    k_gather1<<<3125, 256>>>(b1);                       // 25000 warps, 2 nodes each
    k_dense2<<<DB, 256>>>(w2, Wd2);
    k_gather2_final<<<1563, 256>>>(b2, Wout, bout, out); // 12500 warps, 4 nodes each
}